// round 7
// baseline (speedup 1.0000x reference)
#include <cuda_runtime.h>

#define NN 8192
#define DD 512
#define G  128          // grid; <= SM count so all co-resident
#define TPB 512

// deterministic scratch
__device__ float g_b[DD];
__device__ float g_pm[G], g_pe[G];
__device__ float g_pp[G * DD];
__device__ float g_u[DD];
__device__ float g_v[DD];
// barrier state (replay-safe: count self-resets, gen monotonically increments)
__device__ unsigned g_cnt[4];
__device__ unsigned g_gen[4];

__device__ __forceinline__ void gridbar(int i) {
    __syncthreads();
    if (threadIdx.x == 0) {
        volatile unsigned* gen = &g_gen[i];
        unsigned g0 = *gen;
        __threadfence();
        unsigned my = atomicAdd(&g_cnt[i], 1u);
        if (my == G - 1) {
            g_cnt[i] = 0;
            __threadfence();
            *gen = g0 + 1;
        } else {
            while (*gen == g0) { }
        }
        __threadfence();
    }
    __syncthreads();
}

__global__ void __launch_bounds__(TPB, 1) k_all(
    const float4* __restrict__ X4, const float* __restrict__ W,
    const float* __restrict__ att, float4* __restrict__ out)
{
    __shared__ float4 sb[128];             // 2 KB
    __shared__ float4 sm_p[16][128];       // 32 KB
    __shared__ float sm_m[16], sm_e[16], s_sc[16];
    __shared__ float spm[G], sesc[G];
    __shared__ float sred;
    __shared__ float su[DD];               // 2 KB
    __shared__ float4 sv16[16];
    __shared__ float4 sv[128];             // 2 KB (P3 broadcast)

    int t = threadIdx.x, b = blockIdx.x;
    int w = t >> 5, l = t & 31;
    const float4* W4 = (const float4*)W;

    // ---------- P0: b[k] = sum_o W[k,o]*a2[o]; warp-per-row, k = b*4+w (w<4)
    if (w < 4) {
        int k = b * 4 + w;
        const float4* a4 = (const float4*)(att + DD);
        float4 w0 = W4[k * 128 + l];
        float4 w1 = W4[k * 128 + l + 32];
        float4 w2 = W4[k * 128 + l + 64];
        float4 w3 = W4[k * 128 + l + 96];
        float4 a0 = a4[l], a1 = a4[l + 32], a2v = a4[l + 64], a3 = a4[l + 96];
        float acc0 = (w0.x * a0.x + w0.y * a0.y + w0.z * a0.z + w0.w * a0.w)
                   + (w1.x * a1.x + w1.y * a1.y + w1.z * a1.z + w1.w * a1.w)
                   + (w2.x * a2v.x + w2.y * a2v.y + w2.z * a2v.z + w2.w * a2v.w)
                   + (w3.x * a3.x + w3.y * a3.y + w3.z * a3.z + w3.w * a3.w);
#pragma unroll
        for (int o = 16; o > 0; o >>= 1) acc0 += __shfl_down_sync(~0u, acc0, o);
        if (l == 0) g_b[k] = acc0;
    }
    gridbar(0);

    // ---------- P1: one pass over X; block b owns rows [b*64, b*64+64); warp w: 4 rows
    if (t < 128) sb[t] = ((const float4*)g_b)[t];
    __syncthreads();

    float m = -1e30f, e = 0.f;
    float4 acc[4];
#pragma unroll
    for (int q = 0; q < 4; q++) acc[q] = make_float4(0.f, 0.f, 0.f, 0.f);

    int row0 = b * 64 + w * 4;
#pragma unroll
    for (int i = 0; i < 4; i++) {
        size_t base = (size_t)(row0 + i) * 128;
        float4 x[4];
#pragma unroll
        for (int q = 0; q < 4; q++) x[q] = X4[base + l + 32 * q];
        float d = 0.f;
#pragma unroll
        for (int q = 0; q < 4; q++) {
            float4 bq = sb[l + 32 * q];
            d += x[q].x * bq.x + x[q].y * bq.y + x[q].z * bq.z + x[q].w * bq.w;
        }
#pragma unroll
        for (int o = 16; o > 0; o >>= 1) d += __shfl_xor_sync(~0u, d, o);
        float mn = fmaxf(m, d);
        float cold = expf(m - mn);
        float cs = expf(d - mn);
        e = e * cold + cs;
#pragma unroll
        for (int q = 0; q < 4; q++) {
            acc[q].x = acc[q].x * cold + cs * x[q].x;
            acc[q].y = acc[q].y * cold + cs * x[q].y;
            acc[q].z = acc[q].z * cold + cs * x[q].z;
            acc[q].w = acc[q].w * cold + cs * x[q].w;
        }
        m = mn;
    }
#pragma unroll
    for (int q = 0; q < 4; q++) sm_p[w][l + 32 * q] = acc[q];
    if (l == 0) { sm_m[w] = m; sm_e[w] = e; }
    __syncthreads();

    // block combine: scales once (t<16), then 128 threads combine
    if (t < 16) {
        float mb = sm_m[0];
#pragma unroll
        for (int q = 1; q < 16; q++) mb = fmaxf(mb, sm_m[q]);
        s_sc[t] = expf(sm_m[t] - mb);
        if (t == 0) sred = mb;
    }
    __syncthreads();
    if (t < 128) {
        float4 s = make_float4(0.f, 0.f, 0.f, 0.f);
#pragma unroll
        for (int q = 0; q < 16; q++) {
            float sc = s_sc[q];
            float4 p = sm_p[q][t];
            s.x += sc * p.x; s.y += sc * p.y; s.z += sc * p.z; s.w += sc * p.w;
        }
        ((float4*)(g_pp + b * DD))[t] = s;
    }
    if (t == 0) {
        float eb = 0.f;
#pragma unroll
        for (int q = 0; q < 16; q++) eb += s_sc[q] * sm_e[q];
        g_pm[b] = sred;
        g_pe[b] = eb;
    }
    gridbar(1);

    // ---------- P2a: global max, S, u[k] for k = b*4+w (w<4), scaled 1/S
    if (t < G) spm[t] = g_pm[t];
    __syncthreads();
    if (w == 0) {
        float gm = -1e30f;
#pragma unroll
        for (int q = 0; q < 4; q++) gm = fmaxf(gm, spm[l + 32 * q]);
#pragma unroll
        for (int o = 16; o > 0; o >>= 1) gm = fmaxf(gm, __shfl_xor_sync(~0u, gm, o));
        if (l == 0) sred = gm;
    }
    __syncthreads();
    float gm = sred;
    if (t < G) sesc[t] = expf(spm[t] - gm);
    __syncthreads();
    if (w == 0) {
        float s = 0.f;
#pragma unroll
        for (int q = 0; q < 4; q++) { int p = l + 32 * q; s += sesc[p] * g_pe[p]; }
#pragma unroll
        for (int o = 16; o > 0; o >>= 1) s += __shfl_xor_sync(~0u, s, o);
        if (l == 0) sred = s;
    }
    __syncthreads();
    float inv = 1.f / sred;
    if (w < 4) {
        int k = b * 4 + w;
        float acc2 = 0.f;
#pragma unroll
        for (int q = 0; q < 4; q++) { int p = l + 32 * q; acc2 += sesc[p] * g_pp[p * DD + k]; }
#pragma unroll
        for (int o = 16; o > 0; o >>= 1) acc2 += __shfl_down_sync(~0u, acc2, o);
        if (l == 0) g_u[k] = acc2 * inv;
    }
    gridbar(2);

    // ---------- P2b: block b owns float4 output column b; thread t handles k=t
    su[t] = g_u[t];
    __syncthreads();
    {
        float u = su[t];
        float4 wv = W4[(size_t)t * 128 + b];
        float4 part = make_float4(u * wv.x, u * wv.y, u * wv.z, u * wv.w);
#pragma unroll
        for (int o = 16; o > 0; o >>= 1) {
            part.x += __shfl_down_sync(~0u, part.x, o);
            part.y += __shfl_down_sync(~0u, part.y, o);
            part.z += __shfl_down_sync(~0u, part.z, o);
            part.w += __shfl_down_sync(~0u, part.w, o);
        }
        if (l == 0) sv16[w] = part;
    }
    __syncthreads();
    if (t < 16) {
        float4 p = sv16[t];
#pragma unroll
        for (int o = 8; o > 0; o >>= 1) {
            p.x += __shfl_down_sync(0xFFFFu, p.x, o);
            p.y += __shfl_down_sync(0xFFFFu, p.y, o);
            p.z += __shfl_down_sync(0xFFFFu, p.z, o);
            p.w += __shfl_down_sync(0xFFFFu, p.w, o);
        }
        if (t == 0) ((float4*)g_v)[b] = p;
    }
    gridbar(3);

    // ---------- P3: broadcast store out[i,:] = v (stores need no occupancy)
    if (t < 128) sv[t] = ((const float4*)g_v)[t];
    __syncthreads();
    float4 val = sv[t & 127];        // stride multiple of 128 -> column fixed per thread
    size_t total = (size_t)NN * DD / 4;
    size_t stride = (size_t)G * TPB;
#pragma unroll 4
    for (size_t j = (size_t)b * TPB + t; j < total; j += stride)
        out[j] = val;
}

extern "C" void kernel_launch(void* const* d_in, const int* in_sizes, int n_in,
                              void* d_out, int out_size) {
    const float* X   = (const float*)d_in[0];  // node_features  [8192, 512]
    const float* W   = (const float*)d_in[1];  // weight_matrix  [512, 512]
    const float* att = (const float*)d_in[2];  // attention_vector [1024, 1]
    float* out = (float*)d_out;                // [8192, 512] fp32

    k_all<<<G, TPB>>>((const float4*)X, W, att, (float4*)out);
}

// round 8
// speedup vs baseline: 1.0898x; 1.0898x over previous
#include <cuda_runtime.h>

#define NN 8192
#define DD 512
#define G  128          // k_main grid; <= SM count so all co-resident
#define TPB 512

// deterministic scratch
__device__ float g_b[DD];
__device__ float g_pm[G], g_pe[G];
__device__ float g_pp[G * DD];
__device__ float g_u[DD];
__device__ float g_v[DD];
// barrier state (replay-safe: count self-resets, gen monotonically increments)
__device__ unsigned g_cnt[4];
__device__ unsigned g_gen[4];

__device__ __forceinline__ void gridbar(int i) {
    __syncthreads();
    if (threadIdx.x == 0) {
        volatile unsigned* gen = &g_gen[i];
        unsigned g0 = *gen;
        __threadfence();
        unsigned my = atomicAdd(&g_cnt[i], 1u);
        if (my == G - 1) {
            g_cnt[i] = 0;
            __threadfence();
            *gen = g0 + 1;
        } else {
            while (*gen == g0) { }
        }
        __threadfence();
    }
    __syncthreads();
}

// K1: persistent. P0 (b = W @ a2) -> bar -> P1 (one pass over X, online softmax
// partials) -> bar -> P2a (global S, u) -> bar -> P2b (v).
__global__ void __launch_bounds__(TPB, 1) k_main(
    const float4* __restrict__ X4, const float* __restrict__ W,
    const float* __restrict__ att)
{
    __shared__ float4 sb[128];             // 2 KB
    __shared__ float4 sm_p[16][128];       // 32 KB
    __shared__ float sm_m[16], sm_e[16], s_sc[16];
    __shared__ float spm[G], sesc[G];
    __shared__ float sred;
    __shared__ float su[DD];               // 2 KB
    __shared__ float4 sv16[16];

    int t = threadIdx.x, b = blockIdx.x;
    int w = t >> 5, l = t & 31;
    const float4* W4 = (const float4*)W;

    // ---------- P0: b[k] = sum_o W[k,o]*a2[o]; warp-per-row, k = b*4+w (w<4)
    if (w < 4) {
        int k = b * 4 + w;
        const float4* a4 = (const float4*)(att + DD);
        float4 w0 = W4[k * 128 + l];
        float4 w1 = W4[k * 128 + l + 32];
        float4 w2 = W4[k * 128 + l + 64];
        float4 w3 = W4[k * 128 + l + 96];
        float4 a0 = a4[l], a1 = a4[l + 32], a2v = a4[l + 64], a3 = a4[l + 96];
        float acc0 = (w0.x * a0.x + w0.y * a0.y + w0.z * a0.z + w0.w * a0.w)
                   + (w1.x * a1.x + w1.y * a1.y + w1.z * a1.z + w1.w * a1.w)
                   + (w2.x * a2v.x + w2.y * a2v.y + w2.z * a2v.z + w2.w * a2v.w)
                   + (w3.x * a3.x + w3.y * a3.y + w3.z * a3.z + w3.w * a3.w);
#pragma unroll
        for (int o = 16; o > 0; o >>= 1) acc0 += __shfl_down_sync(~0u, acc0, o);
        if (l == 0) g_b[k] = acc0;
    }
    gridbar(0);

    // ---------- P1: one pass over X; block b owns rows [b*64, b*64+64); warp w: 4 rows
    if (t < 128) sb[t] = ((const float4*)g_b)[t];
    __syncthreads();

    float m = -1e30f, e = 0.f;
    float4 acc[4];
#pragma unroll
    for (int q = 0; q < 4; q++) acc[q] = make_float4(0.f, 0.f, 0.f, 0.f);

    int row0 = b * 64 + w * 4;
#pragma unroll
    for (int i = 0; i < 4; i++) {
        size_t base = (size_t)(row0 + i) * 128;
        float4 x[4];
#pragma unroll
        for (int q = 0; q < 4; q++) x[q] = X4[base + l + 32 * q];
        float d = 0.f;
#pragma unroll
        for (int q = 0; q < 4; q++) {
            float4 bq = sb[l + 32 * q];
            d += x[q].x * bq.x + x[q].y * bq.y + x[q].z * bq.z + x[q].w * bq.w;
        }
#pragma unroll
        for (int o = 16; o > 0; o >>= 1) d += __shfl_xor_sync(~0u, d, o);
        float mn = fmaxf(m, d);
        float cold = expf(m - mn);
        float cs = expf(d - mn);
        e = e * cold + cs;
#pragma unroll
        for (int q = 0; q < 4; q++) {
            acc[q].x = acc[q].x * cold + cs * x[q].x;
            acc[q].y = acc[q].y * cold + cs * x[q].y;
            acc[q].z = acc[q].z * cold + cs * x[q].z;
            acc[q].w = acc[q].w * cold + cs * x[q].w;
        }
        m = mn;
    }
#pragma unroll
    for (int q = 0; q < 4; q++) sm_p[w][l + 32 * q] = acc[q];
    if (l == 0) { sm_m[w] = m; sm_e[w] = e; }
    __syncthreads();

    // block combine: scales once (t<16), then 128 threads combine
    if (t < 16) {
        float mb = sm_m[0];
#pragma unroll
        for (int q = 1; q < 16; q++) mb = fmaxf(mb, sm_m[q]);
        s_sc[t] = expf(sm_m[t] - mb);
        if (t == 0) sred = mb;
    }
    __syncthreads();
    if (t < 128) {
        float4 s = make_float4(0.f, 0.f, 0.f, 0.f);
#pragma unroll
        for (int q = 0; q < 16; q++) {
            float sc = s_sc[q];
            float4 p = sm_p[q][t];
            s.x += sc * p.x; s.y += sc * p.y; s.z += sc * p.z; s.w += sc * p.w;
        }
        ((float4*)(g_pp + b * DD))[t] = s;
    }
    if (t == 0) {
        float eb = 0.f;
#pragma unroll
        for (int q = 0; q < 16; q++) eb += s_sc[q] * sm_e[q];
        g_pm[b] = sred;
        g_pe[b] = eb;
    }
    gridbar(1);

    // ---------- P2a: global max, S, u[k] for k = b*4+w (w<4), scaled 1/S
    if (t < G) spm[t] = g_pm[t];
    __syncthreads();
    if (w == 0) {
        float gm = -1e30f;
#pragma unroll
        for (int q = 0; q < 4; q++) gm = fmaxf(gm, spm[l + 32 * q]);
#pragma unroll
        for (int o = 16; o > 0; o >>= 1) gm = fmaxf(gm, __shfl_xor_sync(~0u, gm, o));
        if (l == 0) sred = gm;
    }
    __syncthreads();
    float gm = sred;
    if (t < G) sesc[t] = expf(spm[t] - gm);
    __syncthreads();
    if (w == 0) {
        float s = 0.f;
#pragma unroll
        for (int q = 0; q < 4; q++) { int p = l + 32 * q; s += sesc[p] * g_pe[p]; }
#pragma unroll
        for (int o = 16; o > 0; o >>= 1) s += __shfl_xor_sync(~0u, s, o);
        if (l == 0) sred = s;
    }
    __syncthreads();
    float inv = 1.f / sred;
    if (w < 4) {
        int k = b * 4 + w;
        float acc2 = 0.f;
#pragma unroll
        for (int q = 0; q < 4; q++) { int p = l + 32 * q; acc2 += sesc[p] * g_pp[p * DD + k]; }
#pragma unroll
        for (int o = 16; o > 0; o >>= 1) acc2 += __shfl_down_sync(~0u, acc2, o);
        if (l == 0) g_u[k] = acc2 * inv;
    }
    gridbar(2);

    // ---------- P2b: block b owns float4 output column b; thread t handles k=t
    su[t] = g_u[t];
    __syncthreads();
    {
        float u = su[t];
        float4 wv = W4[(size_t)t * 128 + b];
        float4 part = make_float4(u * wv.x, u * wv.y, u * wv.z, u * wv.w);
#pragma unroll
        for (int o = 16; o > 0; o >>= 1) {
            part.x += __shfl_down_sync(~0u, part.x, o);
            part.y += __shfl_down_sync(~0u, part.y, o);
            part.z += __shfl_down_sync(~0u, part.z, o);
            part.w += __shfl_down_sync(~0u, part.w, o);
        }
        if (l == 0) sv16[w] = part;
    }
    __syncthreads();
    if (t < 16) {
        float4 p = sv16[t];
#pragma unroll
        for (int o = 8; o > 0; o >>= 1) {
            p.x += __shfl_down_sync(0xFFFFu, p.x, o);
            p.y += __shfl_down_sync(0xFFFFu, p.y, o);
            p.z += __shfl_down_sync(0xFFFFu, p.z, o);
            p.w += __shfl_down_sync(0xFFFFu, p.w, o);
        }
        if (t == 0) ((float4*)g_v)[b] = p;
    }
}

// K2: out[i,:] = v for all i. Full-occupancy streaming store.
__global__ void k_bcast(float4* __restrict__ out) {
    __shared__ float4 sv[128];
    int t = threadIdx.x;
    if (t < 128) sv[t] = ((const float4*)g_v)[t];
    __syncthreads();
    float4 val = sv[t & 127];
    size_t total = (size_t)NN * DD / 4;
    size_t stride = (size_t)gridDim.x * blockDim.x;
    for (size_t j = (size_t)blockIdx.x * blockDim.x + t; j < total; j += stride)
        out[j] = val;
}

extern "C" void kernel_launch(void* const* d_in, const int* in_sizes, int n_in,
                              void* d_out, int out_size) {
    const float* X   = (const float*)d_in[0];  // node_features  [8192, 512]
    const float* W   = (const float*)d_in[1];  // weight_matrix  [512, 512]
    const float* att = (const float*)d_in[2];  // attention_vector [1024, 1]
    float* out = (float*)d_out;                // [8192, 512] fp32

    k_main<<<G, TPB>>>((const float4*)X, W, att);
    k_bcast<<<2048, 256>>>((float4*)out);
}

// round 9
// speedup vs baseline: 1.1192x; 1.0270x over previous
#include <cuda_runtime.h>

#define NN 8192
#define DD 512
#define G  128          // k_main grid; <= SM count so all co-resident
#define TPB 512

// deterministic scratch
__device__ float g_b[DD];
__device__ float g_pm[G], g_pe[G];
__device__ float g_pp[G * DD];
__device__ float g_u[DD];
__device__ float g_v[DD];
// barrier state (replay-safe: count self-resets, gen monotonically increments)
__device__ unsigned g_cnt[4];
__device__ unsigned g_gen[4];

__device__ __forceinline__ void gridbar(int i) {
    __syncthreads();
    if (threadIdx.x == 0) {
        volatile unsigned* gen = &g_gen[i];
        unsigned g0 = *gen;
        __threadfence();
        unsigned my = atomicAdd(&g_cnt[i], 1u);
        if (my == G - 1) {
            g_cnt[i] = 0;
            __threadfence();
            *gen = g0 + 1;
        } else {
            while (*gen == g0) { }
        }
        __threadfence();
    }
    __syncthreads();
}

// K1: b[k] = sum_o W[k,o] * a2[o].  128 blocks x 4 warps, warp-per-row:
// one row per warp, 8 independent float4 loads, covers ~128 SMs.
__global__ void k_b(const float* __restrict__ W, const float* __restrict__ att) {
    const float4* W4 = (const float4*)W;
    const float4* a4 = (const float4*)(att + DD);
    int warp = threadIdx.x >> 5, lane = threadIdx.x & 31;
    int k = blockIdx.x * 4 + warp;           // 0..511
    float4 w0 = W4[k * 128 + lane];
    float4 w1 = W4[k * 128 + lane + 32];
    float4 w2 = W4[k * 128 + lane + 64];
    float4 w3 = W4[k * 128 + lane + 96];
    float4 a0 = a4[lane], a1 = a4[lane + 32], a2v = a4[lane + 64], a3 = a4[lane + 96];
    float acc = (w0.x * a0.x + w0.y * a0.y + w0.z * a0.z + w0.w * a0.w)
              + (w1.x * a1.x + w1.y * a1.y + w1.z * a1.z + w1.w * a1.w)
              + (w2.x * a2v.x + w2.y * a2v.y + w2.z * a2v.z + w2.w * a2v.w)
              + (w3.x * a3.x + w3.y * a3.y + w3.z * a3.z + w3.w * a3.w);
#pragma unroll
    for (int o = 16; o > 0; o >>= 1) acc += __shfl_down_sync(~0u, acc, o);
    if (lane == 0) g_b[k] = acc;
}

// K2: persistent: P1 one pass over X (online softmax partials) -> bar ->
// P2a global S + u -> bar -> P2b v.
__global__ void __launch_bounds__(TPB, 1) k_main(
    const float4* __restrict__ X4, const float* __restrict__ W)
{
    __shared__ float4 sb[128];             // 2 KB
    __shared__ float4 sm_p[16][128];       // 32 KB
    __shared__ float sm_m[16], sm_e[16], s_sc[16];
    __shared__ float spm[G], sesc[G];
    __shared__ float sred;
    __shared__ float su[DD];               // 2 KB
    __shared__ float4 sv16[16];

    int t = threadIdx.x, b = blockIdx.x;
    int w = t >> 5, l = t & 31;
    const float4* W4 = (const float4*)W;

    // ---------- P1: block b owns rows [b*64, b*64+64); warp w owns 4 rows.
    if (t < 128) sb[t] = ((const float4*)g_b)[t];
    __syncthreads();

    float m = -1e30f, e = 0.f;
    float4 acc[4];
#pragma unroll
    for (int q = 0; q < 4; q++) acc[q] = make_float4(0.f, 0.f, 0.f, 0.f);

    int row0 = b * 64 + w * 4;
#pragma unroll
    for (int i = 0; i < 4; i++) {
        size_t base = (size_t)(row0 + i) * 128;
        float4 x[4];
#pragma unroll
        for (int q = 0; q < 4; q++) x[q] = X4[base + l + 32 * q];
        float d = 0.f;
#pragma unroll
        for (int q = 0; q < 4; q++) {
            float4 bq = sb[l + 32 * q];
            d += x[q].x * bq.x + x[q].y * bq.y + x[q].z * bq.z + x[q].w * bq.w;
        }
#pragma unroll
        for (int o = 16; o > 0; o >>= 1) d += __shfl_xor_sync(~0u, d, o);
        float mn = fmaxf(m, d);
        float cold = expf(m - mn);
        float cs = expf(d - mn);
        e = e * cold + cs;
#pragma unroll
        for (int q = 0; q < 4; q++) {
            acc[q].x = acc[q].x * cold + cs * x[q].x;
            acc[q].y = acc[q].y * cold + cs * x[q].y;
            acc[q].z = acc[q].z * cold + cs * x[q].z;
            acc[q].w = acc[q].w * cold + cs * x[q].w;
        }
        m = mn;
    }
#pragma unroll
    for (int q = 0; q < 4; q++) sm_p[w][l + 32 * q] = acc[q];
    if (l == 0) { sm_m[w] = m; sm_e[w] = e; }
    __syncthreads();

    // block combine: scales computed once (t<16), then 128 threads combine
    if (t < 16) {
        float mb = sm_m[0];
#pragma unroll
        for (int q = 1; q < 16; q++) mb = fmaxf(mb, sm_m[q]);
        s_sc[t] = expf(sm_m[t] - mb);
        if (t == 0) sred = mb;
    }
    __syncthreads();
    if (t < 128) {
        float4 s = make_float4(0.f, 0.f, 0.f, 0.f);
#pragma unroll
        for (int q = 0; q < 16; q++) {
            float sc = s_sc[q];
            float4 p = sm_p[q][t];
            s.x += sc * p.x; s.y += sc * p.y; s.z += sc * p.z; s.w += sc * p.w;
        }
        ((float4*)(g_pp + b * DD))[t] = s;
    }
    if (t == 0) {
        float eb = 0.f;
#pragma unroll
        for (int q = 0; q < 16; q++) eb += s_sc[q] * sm_e[q];
        g_pm[b] = sred;
        g_pe[b] = eb;
    }
    gridbar(0);

    // ---------- P2a: global max, S, u[k] for k = b*4+w (w<4), scaled 1/S
    if (t < G) spm[t] = g_pm[t];
    __syncthreads();
    if (w == 0) {
        float gm = -1e30f;
#pragma unroll
        for (int q = 0; q < 4; q++) gm = fmaxf(gm, spm[l + 32 * q]);
#pragma unroll
        for (int o = 16; o > 0; o >>= 1) gm = fmaxf(gm, __shfl_xor_sync(~0u, gm, o));
        if (l == 0) sred = gm;
    }
    __syncthreads();
    float gm = sred;
    if (t < G) sesc[t] = expf(spm[t] - gm);
    __syncthreads();
    if (w == 0) {
        float s = 0.f;
#pragma unroll
        for (int q = 0; q < 4; q++) { int p = l + 32 * q; s += sesc[p] * g_pe[p]; }
#pragma unroll
        for (int o = 16; o > 0; o >>= 1) s += __shfl_xor_sync(~0u, s, o);
        if (l == 0) sred = s;
    }
    __syncthreads();
    float inv = 1.f / sred;
    if (w < 4) {
        int k = b * 4 + w;
        float acc2 = 0.f;
#pragma unroll
        for (int q = 0; q < 4; q++) { int p = l + 32 * q; acc2 += sesc[p] * g_pp[p * DD + k]; }
#pragma unroll
        for (int o = 16; o > 0; o >>= 1) acc2 += __shfl_down_sync(~0u, acc2, o);
        if (l == 0) g_u[k] = acc2 * inv;
    }
    gridbar(1);

    // ---------- P2b: block b owns float4 output column b; thread t handles k=t.
    su[t] = g_u[t];
    __syncthreads();
    {
        float u = su[t];
        float4 wv = W4[(size_t)t * 128 + b];
        float4 part = make_float4(u * wv.x, u * wv.y, u * wv.z, u * wv.w);
#pragma unroll
        for (int o = 16; o > 0; o >>= 1) {
            part.x += __shfl_down_sync(~0u, part.x, o);
            part.y += __shfl_down_sync(~0u, part.y, o);
            part.z += __shfl_down_sync(~0u, part.z, o);
            part.w += __shfl_down_sync(~0u, part.w, o);
        }
        if (l == 0) sv16[w] = part;
    }
    __syncthreads();
    if (t < 16) {
        float4 p = sv16[t];
#pragma unroll
        for (int o = 8; o > 0; o >>= 1) {
            p.x += __shfl_down_sync(0xFFFFu, p.x, o);
            p.y += __shfl_down_sync(0xFFFFu, p.y, o);
            p.z += __shfl_down_sync(0xFFFFu, p.z, o);
            p.w += __shfl_down_sync(0xFFFFu, p.w, o);
        }
        if (t == 0) ((float4*)g_v)[b] = p;
    }
}

// K3: out[i,:] = v. 512 blocks x 256 threads, 8 fully-unrolled stores per
// thread (512*256*8 = 1,048,576 float4 exactly -> no bounds check).
__global__ void k_bcast(float4* __restrict__ out) {
    __shared__ float4 sv[128];
    int t = threadIdx.x;
    if (t < 128) sv[t] = ((const float4*)g_v)[t];
    __syncthreads();
    float4 val = sv[t & 127];
    size_t base = (size_t)blockIdx.x * (256 * 8) + t;
#pragma unroll
    for (int i = 0; i < 8; i++)
        out[base + (size_t)i * 256] = val;
}

extern "C" void kernel_launch(void* const* d_in, const int* in_sizes, int n_in,
                              void* d_out, int out_size) {
    const float* X   = (const float*)d_in[0];  // node_features  [8192, 512]
    const float* W   = (const float*)d_in[1];  // weight_matrix  [512, 512]
    const float* att = (const float*)d_in[2];  // attention_vector [1024, 1]
    float* out = (float*)d_out;                // [8192, 512] fp32

    k_b<<<128, 128>>>(W, att);
    k_main<<<G, TPB>>>((const float4*)X, W);
    k_bcast<<<512, 256>>>((float4*)out);
}

// round 10
// speedup vs baseline: 1.1485x; 1.0261x over previous
#include <cuda_runtime.h>

#define NN 8192
#define DD 512
#define G  128          // k_main grid; <= SM count so all co-resident
#define TPB 512

// deterministic scratch
__device__ float g_b[DD];
__device__ float g_pm[G], g_pe[G];
__device__ float g_pp[G * DD];
__device__ float g_u[DD];
__device__ float g_v[DD];
// barrier state (replay-safe: count self-resets, gen monotonically increments)
__device__ unsigned g_cnt[4];
__device__ unsigned g_gen[4];

__device__ __forceinline__ void gridbar(int i) {
    __syncthreads();
    if (threadIdx.x == 0) {
        volatile unsigned* gen = &g_gen[i];
        unsigned g0 = *gen;
        __threadfence();
        unsigned my = atomicAdd(&g_cnt[i], 1u);
        if (my == G - 1) {
            g_cnt[i] = 0;
            __threadfence();
            *gen = g0 + 1;
        } else {
            while (*gen == g0) { }
        }
        __threadfence();
    }
    __syncthreads();
}

// K1: b[k] = sum_o W[k,o] * a2[o]. 128 blocks x 4 warps, warp-per-row.
// (Also serves as the ramp absorber for each graph replay.)
__global__ void k_b(const float* __restrict__ W, const float* __restrict__ att) {
    const float4* W4 = (const float4*)W;
    const float4* a4 = (const float4*)(att + DD);
    int warp = threadIdx.x >> 5, lane = threadIdx.x & 31;
    int k = blockIdx.x * 4 + warp;           // 0..511
    float4 w0 = W4[k * 128 + lane];
    float4 w1 = W4[k * 128 + lane + 32];
    float4 w2 = W4[k * 128 + lane + 64];
    float4 w3 = W4[k * 128 + lane + 96];
    float4 a0 = a4[lane], a1 = a4[lane + 32], a2v = a4[lane + 64], a3 = a4[lane + 96];
    float acc = (w0.x * a0.x + w0.y * a0.y + w0.z * a0.z + w0.w * a0.w)
              + (w1.x * a1.x + w1.y * a1.y + w1.z * a1.z + w1.w * a1.w)
              + (w2.x * a2v.x + w2.y * a2v.y + w2.z * a2v.z + w2.w * a2v.w)
              + (w3.x * a3.x + w3.y * a3.y + w3.z * a3.z + w3.w * a3.w);
#pragma unroll
    for (int o = 16; o > 0; o >>= 1) acc += __shfl_down_sync(~0u, acc, o);
    if (lane == 0) g_b[k] = acc;
}

// K2: persistent: P1 one pass over X -> bar -> P2a global S + u -> bar -> P2b v.
__global__ void __launch_bounds__(TPB, 1) k_main(
    const float4* __restrict__ X4, const float* __restrict__ W)
{
    __shared__ float4 sb[128];             // 2 KB
    __shared__ float4 sm_p[16][128];       // 32 KB
    __shared__ float sm_m[16], sm_e[16], s_sc[16];
    __shared__ float spm[G], sesc[G];
    __shared__ float sred;
    __shared__ float su[DD];               // 2 KB
    __shared__ float4 sv16[16];

    int t = threadIdx.x, b = blockIdx.x;
    int w = t >> 5, l = t & 31;
    const float4* W4 = (const float4*)W;

    // ---------- P1: block b owns rows [b*64, b*64+64); warp w owns 4 rows.
    // NO online softmax: all 4 rows live in registers. 16 independent loads
    // (MLP 16), 4 independent dot chains, 4-wide interleaved shfl reduce.
    if (t < 128) sb[t] = ((const float4*)g_b)[t];
    __syncthreads();

    float4 x[4][4];
    {
        size_t base = (size_t)(b * 64 + w * 4) * 128 + l;
#pragma unroll
        for (int i = 0; i < 4; i++)
#pragma unroll
            for (int q = 0; q < 4; q++)
                x[i][q] = X4[base + (size_t)i * 128 + 32 * q];
    }
    float d0 = 0.f, d1 = 0.f, d2 = 0.f, d3 = 0.f;
#pragma unroll
    for (int q = 0; q < 4; q++) {
        float4 bq = sb[l + 32 * q];
        d0 += x[0][q].x * bq.x + x[0][q].y * bq.y + x[0][q].z * bq.z + x[0][q].w * bq.w;
        d1 += x[1][q].x * bq.x + x[1][q].y * bq.y + x[1][q].z * bq.z + x[1][q].w * bq.w;
        d2 += x[2][q].x * bq.x + x[2][q].y * bq.y + x[2][q].z * bq.z + x[2][q].w * bq.w;
        d3 += x[3][q].x * bq.x + x[3][q].y * bq.y + x[3][q].z * bq.z + x[3][q].w * bq.w;
    }
#pragma unroll
    for (int o = 16; o > 0; o >>= 1) {     // 4 independent chains, overlapped
        d0 += __shfl_xor_sync(~0u, d0, o);
        d1 += __shfl_xor_sync(~0u, d1, o);
        d2 += __shfl_xor_sync(~0u, d2, o);
        d3 += __shfl_xor_sync(~0u, d3, o);
    }
    float m = fmaxf(fmaxf(d0, d1), fmaxf(d2, d3));
    float c0 = expf(d0 - m), c1 = expf(d1 - m), c2 = expf(d2 - m), c3 = expf(d3 - m);
    float e = (c0 + c1) + (c2 + c3);
#pragma unroll
    for (int q = 0; q < 4; q++) {
        float4 s;
        s.x = c0 * x[0][q].x + c1 * x[1][q].x + c2 * x[2][q].x + c3 * x[3][q].x;
        s.y = c0 * x[0][q].y + c1 * x[1][q].y + c2 * x[2][q].y + c3 * x[3][q].y;
        s.z = c0 * x[0][q].z + c1 * x[1][q].z + c2 * x[2][q].z + c3 * x[3][q].z;
        s.w = c0 * x[0][q].w + c1 * x[1][q].w + c2 * x[2][q].w + c3 * x[3][q].w;
        sm_p[w][l + 32 * q] = s;
    }
    if (l == 0) { sm_m[w] = m; sm_e[w] = e; }
    __syncthreads();

    // block combine: scales once (t<16), then 128 threads combine
    if (t < 16) {
        float mb = sm_m[0];
#pragma unroll
        for (int q = 1; q < 16; q++) mb = fmaxf(mb, sm_m[q]);
        s_sc[t] = expf(sm_m[t] - mb);
        if (t == 0) sred = mb;
    }
    __syncthreads();
    if (t < 128) {
        float4 s = make_float4(0.f, 0.f, 0.f, 0.f);
#pragma unroll
        for (int q = 0; q < 16; q++) {
            float sc = s_sc[q];
            float4 p = sm_p[q][t];
            s.x += sc * p.x; s.y += sc * p.y; s.z += sc * p.z; s.w += sc * p.w;
        }
        ((float4*)(g_pp + b * DD))[t] = s;
    }
    if (t == 0) {
        float eb = 0.f;
#pragma unroll
        for (int q = 0; q < 16; q++) eb += s_sc[q] * sm_e[q];
        g_pm[b] = sred;
        g_pe[b] = eb;
    }
    gridbar(0);

    // ---------- P2a: global max, S, u[k] for k = b*4+w (w<4), scaled 1/S
    if (t < G) spm[t] = g_pm[t];
    __syncthreads();
    if (w == 0) {
        float gm = -1e30f;
#pragma unroll
        for (int q = 0; q < 4; q++) gm = fmaxf(gm, spm[l + 32 * q]);
#pragma unroll
        for (int o = 16; o > 0; o >>= 1) gm = fmaxf(gm, __shfl_xor_sync(~0u, gm, o));
        if (l == 0) sred = gm;
    }
    __syncthreads();
    float gm = sred;
    if (t < G) sesc[t] = expf(spm[t] - gm);
    __syncthreads();
    if (w == 0) {
        float s = 0.f;
#pragma unroll
        for (int q = 0; q < 4; q++) { int p = l + 32 * q; s += sesc[p] * g_pe[p]; }
#pragma unroll
        for (int o = 16; o > 0; o >>= 1) s += __shfl_xor_sync(~0u, s, o);
        if (l == 0) sred = s;
    }
    __syncthreads();
    float inv = 1.f / sred;
    if (w < 4) {
        int k = b * 4 + w;
        float acc2 = 0.f;
#pragma unroll
        for (int q = 0; q < 4; q++) { int p = l + 32 * q; acc2 += sesc[p] * g_pp[p * DD + k]; }
#pragma unroll
        for (int o = 16; o > 0; o >>= 1) acc2 += __shfl_down_sync(~0u, acc2, o);
        if (l == 0) g_u[k] = acc2 * inv;
    }
    gridbar(1);

    // ---------- P2b: block b owns float4 output column b; thread t handles k=t.
    su[t] = g_u[t];
    __syncthreads();
    {
        float u = su[t];
        float4 wv = W4[(size_t)t * 128 + b];
        float4 part = make_float4(u * wv.x, u * wv.y, u * wv.z, u * wv.w);
#pragma unroll
        for (int o = 16; o > 0; o >>= 1) {
            part.x += __shfl_down_sync(~0u, part.x, o);
            part.y += __shfl_down_sync(~0u, part.y, o);
            part.z += __shfl_down_sync(~0u, part.z, o);
            part.w += __shfl_down_sync(~0u, part.w, o);
        }
        if (l == 0) sv16[w] = part;
    }
    __syncthreads();
    if (t < 16) {
        float4 p = sv16[t];
#pragma unroll
        for (int o = 8; o > 0; o >>= 1) {
            p.x += __shfl_down_sync(0xFFFFu, p.x, o);
            p.y += __shfl_down_sync(0xFFFFu, p.y, o);
            p.z += __shfl_down_sync(0xFFFFu, p.z, o);
            p.w += __shfl_down_sync(0xFFFFu, p.w, o);
        }
        if (t == 0) ((float4*)g_v)[b] = p;
    }
}

// K3: out[i,:] = v. 512 blocks x 256 threads, 8 fully-unrolled stores per
// thread (512*256*8 = 1,048,576 float4 exactly -> no bounds check).
__global__ void k_bcast(float4* __restrict__ out) {
    __shared__ float4 sv[128];
    int t = threadIdx.x;
    if (t < 128) sv[t] = ((const float4*)g_v)[t];
    __syncthreads();
    float4 val = sv[t & 127];
    size_t base = (size_t)blockIdx.x * (256 * 8) + t;
#pragma unroll
    for (int i = 0; i < 8; i++)
        out[base + (size_t)i * 256] = val;
}

extern "C" void kernel_launch(void* const* d_in, const int* in_sizes, int n_in,
                              void* d_out, int out_size) {
    const float* X   = (const float*)d_in[0];  // node_features  [8192, 512]
    const float* W   = (const float*)d_in[1];  // weight_matrix  [512, 512]
    const float* att = (const float*)d_in[2];  // attention_vector [1024, 1]
    float* out = (float*)d_out;                // [8192, 512] fp32

    k_b<<<128, 128>>>(W, att);
    k_main<<<G, TPB>>>((const float4*)X, W);
    k_bcast<<<512, 256>>>((float4*)out);
}